// round 5
// baseline (speedup 1.0000x reference)
#include <cuda_runtime.h>

#define NN 50000
#define EE 300000
#define RR 4
#define FIN 11
#define HH 256
#define GG 2048
#define TT 19
#define RH 1024   // R*H
#define BN_EPS 1e-5f

// ---------------- scratch (device globals; no allocations allowed) ----------------
__device__ float g_B[(size_t)RR * NN * HH];       // per-relation (x + agg), max fin=256
__device__ float g_Hcat[(size_t)NN * RH];         // [N, R*H] relation hidden states
__device__ float g_X0[(size_t)NN * HH];
__device__ float g_X1[(size_t)NN * HH];
__device__ float g_OUT[(size_t)NN * HH];
__device__ float g_sums[2 * RH];                  // col sums / sumsq
__device__ float g_scale[RH];
__device__ float g_shift[RH];
__device__ float g_bias0[HH];
__device__ float g_pool[GG * HH];
__device__ float g_cnt[GG];

// int32 copies of the index tensors (robust to harness int32-vs-int64)
__device__ int g_ei[2 * EE];
__device__ int g_et[EE];
__device__ int g_batch[NN];

// ---------------- index dtype sniff + convert ----------------
// If input really is int64 (values < 2^31, little-endian), odd 32-bit words are 0.
// For int32 data, edge_index words 1,3,5,7 are uniform [0,50000): P(all zero) ~ 0.
__global__ void convert_idx(const int* __restrict__ ei_raw,
                            const int* __restrict__ et_raw,
                            const int* __restrict__ b_raw) {
    bool is64 = (ei_raw[1] == 0 && ei_raw[3] == 0 && ei_raw[5] == 0 && ei_raw[7] == 0);
    int i = blockIdx.x * blockDim.x + threadIdx.x;
    int stride = gridDim.x * blockDim.x;
    for (int j = i; j < 2 * EE; j += stride) g_ei[j] = is64 ? ei_raw[2 * j] : ei_raw[j];
    for (int j = i; j < EE; j += stride)     g_et[j] = is64 ? et_raw[2 * j] : et_raw[j];
    for (int j = i; j < NN; j += stride)     g_batch[j] = is64 ? b_raw[2 * j] : b_raw[j];
}

// ---------------- helpers ----------------

// Replicate X (size N*fin) into the R slots of g_B.
__global__ void copyB_kernel(const float* __restrict__ X, int fin) {
    size_t per = (size_t)NN * fin / 4;
    size_t tot = per * RR;
    const float4* X4 = (const float4*)X;
    float4* B4 = (float4*)g_B;
    for (size_t i = (size_t)blockIdx.x * blockDim.x + threadIdx.x; i < tot;
         i += (size_t)gridDim.x * blockDim.x) {
        B4[i] = X4[i % per];
    }
}

// Scatter-add edges, fin == 256. One block per edge, one thread per feature.
__global__ void scatter_f256(const float* __restrict__ X) {
    int e = blockIdx.x;
    int k = threadIdx.x;
    int s = g_ei[e];
    int d = g_ei[EE + e];
    int r = g_et[e];
    atomicAdd(&g_B[((size_t)r * NN + d) * HH + k], X[(size_t)s * HH + k]);
}

// Scatter-add edges, fin == 11 (layer 1). 16 threads per edge, k<11 active.
__global__ void scatter_f11(const float* __restrict__ X) {
    int gid = blockIdx.x * blockDim.x + threadIdx.x;
    int e = gid >> 4;
    int k = gid & 15;
    if (e >= EE || k >= FIN) return;
    int s = g_ei[e];
    int d = g_ei[EE + e];
    int r = g_et[e];
    atomicAdd(&g_B[((size_t)r * NN + d) * FIN + k], X[(size_t)s * FIN + k]);
}

// ---------------- generic fp32 SGEMM: 64x64 tile, 4x4 per thread ----------------
#define BM 64
#define BN 64
#define BK 16

__global__ void __launch_bounds__(256)
sgemm(const float* __restrict__ A, int M, int K, int lda, size_t bsA,
      const float* __restrict__ W, int ldw, size_t bsW,
      const float* __restrict__ Crd, float* __restrict__ Cwr,
      int ldc, int bsC,
      const float* __restrict__ bias, int relu)
{
    int bz = blockIdx.z;
    A += (size_t)bz * bsA;
    W += (size_t)bz * bsW;

    int rowBase = blockIdx.y * BM;
    int colTile = blockIdx.x * BN;   // local column within this batch's Hout

    __shared__ float As[BK][BM + 1];
    __shared__ float Bs[BK][BN + 1];

    int tid = threadIdx.x;
    int tx = tid & 15;
    int ty = tid >> 4;

    float acc[4][4] = {};

    for (int k0 = 0; k0 < K; k0 += BK) {
        // load A tile (64 x 16), transposed into As[k][m]
        {
            int k = tid & 15;
            int m = tid >> 4;
#pragma unroll
            for (int p = 0; p < 4; p++) {
                int lm = m + p * 16;
                int row = rowBase + lm;
                float v = 0.f;
                if (row < M && (k0 + k) < K) v = A[(size_t)row * lda + k0 + k];
                As[k][lm] = v;
            }
        }
        // load W tile (16 x 64)
        {
            int n = tid & 63;
            int kq = tid >> 6;
#pragma unroll
            for (int p = 0; p < 4; p++) {
                int kk = kq + p * 4;
                float v = 0.f;
                if ((k0 + kk) < K) v = W[(size_t)(k0 + kk) * ldw + colTile + n];
                Bs[kk][n] = v;
            }
        }
        __syncthreads();

#pragma unroll
        for (int kk = 0; kk < BK; kk++) {
            float a[4], b[4];
#pragma unroll
            for (int i = 0; i < 4; i++) a[i] = As[kk][ty * 4 + i];
#pragma unroll
            for (int j = 0; j < 4; j++) b[j] = Bs[kk][tx * 4 + j];
#pragma unroll
            for (int i = 0; i < 4; i++)
#pragma unroll
                for (int j = 0; j < 4; j++)
                    acc[i][j] += a[i] * b[j];
        }
        __syncthreads();
    }

#pragma unroll
    for (int i = 0; i < 4; i++) {
        int row = rowBase + ty * 4 + i;
        if (row >= M) continue;
#pragma unroll
        for (int j = 0; j < 4; j++) {
            int lcol = colTile + tx * 4 + j;
            size_t idx = (size_t)row * ldc + bz * bsC + lcol;
            float v = acc[i][j];
            if (bias) v += bias[lcol];
            if (Crd) v += Crd[idx];
            if (relu) v = fmaxf(v, 0.f);
            Cwr[idx] = v;
        }
    }
}

// ---------------- BatchNorm ----------------
__global__ void zero_stats() {
    int i = blockIdx.x * blockDim.x + threadIdx.x;
    if (i < 2 * RH) g_sums[i] = 0.f;
}

__global__ void bn_stats(const float* __restrict__ Hc) {
    int col = blockIdx.x * blockDim.x + threadIdx.x;  // gridDim.x*256 == RH
    float s = 0.f, q = 0.f;
    for (int row = blockIdx.y; row < NN; row += gridDim.y) {
        float v = Hc[(size_t)row * RH + col];
        s += v;
        q += v * v;
    }
    atomicAdd(&g_sums[col], s);
    atomicAdd(&g_sums[RH + col], q);
}

__global__ void bn_finalize(const float* __restrict__ g, const float* __restrict__ bt) {
    int c = blockIdx.x * blockDim.x + threadIdx.x;
    if (c < RH) {
        float mu  = g_sums[c] * (1.0f / NN);
        float var = g_sums[RH + c] * (1.0f / NN) - mu * mu;
        float sc  = g[c] * rsqrtf(var + BN_EPS);
        g_scale[c] = sc;
        g_shift[c] = bt[c] - mu * sc;
    }
}

__global__ void bn_apply() {
    size_t tot = (size_t)NN * RH / 4;
    float4* H4 = (float4*)g_Hcat;
    for (size_t i = (size_t)blockIdx.x * blockDim.x + threadIdx.x; i < tot;
         i += (size_t)gridDim.x * blockDim.x) {
        int c = ((int)(i & (RH / 4 - 1))) * 4;
        float4 v = H4[i];
        v.x = fmaxf(fmaf(v.x, g_scale[c + 0], g_shift[c + 0]), 0.f);
        v.y = fmaxf(fmaf(v.y, g_scale[c + 1], g_shift[c + 1]), 0.f);
        v.z = fmaxf(fmaf(v.z, g_scale[c + 2], g_shift[c + 2]), 0.f);
        v.w = fmaxf(fmaf(v.w, g_scale[c + 3], g_shift[c + 3]), 0.f);
        H4[i] = v;
    }
}

// bias0 = sb + sum_r b2_r   (b1 cancels inside BN, so it's dropped)
__global__ void bias0_kernel(const float* __restrict__ sb, const float* __restrict__ b2) {
    int c = threadIdx.x;
    g_bias0[c] = sb[c] + b2[c] + b2[HH + c] + b2[2 * HH + c] + b2[3 * HH + c];
}

// ---------------- pooling + final linear ----------------
__global__ void pool_zero() {
    int i = blockIdx.x * blockDim.x + threadIdx.x;
    if (i < GG * HH) g_pool[i] = 0.f;
    if (i < GG) g_cnt[i] = 0.f;
}

__global__ void pool_scatter(const float* __restrict__ X) {
    int n = blockIdx.x;
    int c = threadIdx.x;
    int b = g_batch[n];
    atomicAdd(&g_pool[b * HH + c], X[(size_t)n * HH + c]);
    if (c == 0) atomicAdd(&g_cnt[b], 1.f);
}

__global__ void final_linear(const float* __restrict__ lw, const float* __restrict__ lb,
                             float* __restrict__ out) {
    __shared__ float sh[HH];
    int g = blockIdx.x;
    float inv = 1.0f / fmaxf(g_cnt[g], 1.f);
    sh[threadIdx.x] = g_pool[g * HH + threadIdx.x] * inv;
    __syncthreads();
    if (threadIdx.x < TT) {
        int t = threadIdx.x;
        float acc = lb[t];
#pragma unroll 8
        for (int c = 0; c < HH; c++) acc += sh[c] * lw[c * TT + t];
        out[g * TT + t] = acc;
    }
}

// ---------------- orchestration ----------------
static void run_layer(const float* Xin, int fin,
                      const float* sw, const float* sb, const float* w1,
                      const float* gamma, const float* beta,
                      const float* w2, const float* b2,
                      float* pB, float* pHcat, float* pOUT, float* pBias0,
                      float* Xout)
{
    // 1. B[r] = X; B[r][dst] += X[src] over edges of type r
    copyB_kernel<<<4096, 256>>>(Xin, fin);
    if (fin == HH) {
        scatter_f256<<<EE, HH>>>(Xin);
    } else {
        scatter_f11<<<(EE * 16 + 255) / 256, 256>>>(Xin);
    }

    int mtiles = (NN + BM - 1) / BM;

    // 2. Hcat[:, r*H:(r+1)*H] = B[r] @ w1[r]    (b1 dropped: cancels in BN)
    sgemm<<<dim3(HH / BN, mtiles, RR), 256>>>(
        pB, NN, fin, fin, (size_t)NN * fin,
        w1, HH, (size_t)fin * HH,
        nullptr, pHcat, RH, HH, nullptr, 0);

    // 3. BatchNorm (training stats) + ReLU, in place on Hcat
    zero_stats<<<2, 1024>>>();
    bn_stats<<<dim3(RH / 256, 128), 256>>>(pHcat);
    bn_finalize<<<4, 256>>>(gamma, beta);
    bn_apply<<<4096, 256>>>();

    // 4. bias0 = sb + sum_r b2_r
    bias0_kernel<<<1, 256>>>(sb, b2);

    // 5. OUT = Xin @ sw + bias0
    sgemm<<<dim3(HH / BN, mtiles, 1), 256>>>(
        Xin, NN, fin, fin, 0,
        sw, HH, 0,
        nullptr, pOUT, HH, 0, pBias0, 0);

    // 6. Xout = relu(OUT + Hcat @ W2cat)   (W2 stacked [R*H, H] is contiguous)
    sgemm<<<dim3(HH / BN, mtiles, 1), 256>>>(
        pHcat, NN, RH, RH, 0,
        w2, HH, 0,
        pOUT, Xout, HH, 0, nullptr, 1);
}

extern "C" void kernel_launch(void* const* d_in, const int* in_sizes, int n_in,
                              void* d_out, int out_size)
{
    const float* x     = (const float*)d_in[0];
    const int*   ei    = (const int*)d_in[1];   // int32 OR int64 raw words (sniffed)
    const int*   et    = (const int*)d_in[2];
    const int*   batch = (const int*)d_in[3];
    const float* lin_w = (const float*)d_in[28];
    const float* lin_b = (const float*)d_in[29];

    float *pB, *pHcat, *pX0, *pX1, *pOUT, *pBias0;
    cudaGetSymbolAddress((void**)&pB, g_B);
    cudaGetSymbolAddress((void**)&pHcat, g_Hcat);
    cudaGetSymbolAddress((void**)&pX0, g_X0);
    cudaGetSymbolAddress((void**)&pX1, g_X1);
    cudaGetSymbolAddress((void**)&pOUT, g_OUT);
    cudaGetSymbolAddress((void**)&pBias0, g_bias0);

    // normalize indices to int32 scratch (handles int32 or int64 inputs)
    convert_idx<<<1024, 256>>>(ei, et, batch);

    // layer params: base = 4 + 8*l : sw, sb, w1, b1(unused), g, bt, w2, b2
    const float* Xcur = x;
    float* outs[3] = {pX0, pX1, pX0};
    int fins[3] = {FIN, HH, HH};
    for (int l = 0; l < 3; l++) {
        int base = 4 + 8 * l;
        run_layer(Xcur, fins[l],
                  (const float*)d_in[base + 0], (const float*)d_in[base + 1],
                  (const float*)d_in[base + 2],
                  (const float*)d_in[base + 4], (const float*)d_in[base + 5],
                  (const float*)d_in[base + 6], (const float*)d_in[base + 7],
                  pB, pHcat, pOUT, pBias0, outs[l]);
        Xcur = outs[l];
    }

    // global mean pool + final linear
    pool_zero<<<(GG * HH + 255) / 256, 256>>>();
    pool_scatter<<<NN, HH>>>(Xcur);
    final_linear<<<GG, HH>>>(lin_w, lin_b, (float*)d_out);
}

// round 6
// speedup vs baseline: 1.9379x; 1.9379x over previous
#include <cuda_runtime.h>

#define NN 50000
#define EE 300000
#define RR 4
#define FIN 11
#define HH 256
#define GG 2048
#define TT 19
#define RH 1024   // R*H
#define BN_EPS 1e-5f

// ---------------- scratch (device globals; no allocations allowed) ----------------
__device__ float g_B[(size_t)RR * NN * HH];       // per-relation (x + agg), max fin=256
__device__ float g_Hcat[(size_t)NN * RH];         // [N, R*H] relation hidden states
__device__ float g_X0[(size_t)NN * HH];
__device__ float g_X1[(size_t)NN * HH];
__device__ float g_OUT[(size_t)NN * HH];
__device__ float g_sums[2 * RH];                  // col sums / sumsq
__device__ float g_scale[RH];
__device__ float g_shift[RH];
__device__ float g_bias0[HH];
__device__ float g_pool[GG * HH];
__device__ float g_cnt[GG];

// int32 copies of the index tensors (robust to harness int32-vs-int64)
__device__ int g_ei[2 * EE];
__device__ int g_et[EE];
__device__ int g_batch[NN];

// ---------------- index dtype sniff + convert ----------------
__global__ void convert_idx(const int* __restrict__ ei_raw,
                            const int* __restrict__ et_raw,
                            const int* __restrict__ b_raw) {
    bool is64 = (ei_raw[1] == 0 && ei_raw[3] == 0 && ei_raw[5] == 0 && ei_raw[7] == 0);
    int i = blockIdx.x * blockDim.x + threadIdx.x;
    int stride = gridDim.x * blockDim.x;
    for (int j = i; j < 2 * EE; j += stride) g_ei[j] = is64 ? ei_raw[2 * j] : ei_raw[j];
    for (int j = i; j < EE; j += stride)     g_et[j] = is64 ? et_raw[2 * j] : et_raw[j];
    for (int j = i; j < NN; j += stride)     g_batch[j] = is64 ? b_raw[2 * j] : b_raw[j];
}

// ---------------- helpers ----------------
__global__ void copyB_kernel(const float* __restrict__ X, int fin) {
    size_t per = (size_t)NN * fin / 4;
    size_t tot = per * RR;
    const float4* X4 = (const float4*)X;
    float4* B4 = (float4*)g_B;
    for (size_t i = (size_t)blockIdx.x * blockDim.x + threadIdx.x; i < tot;
         i += (size_t)gridDim.x * blockDim.x) {
        B4[i] = X4[i % per];
    }
}

__global__ void scatter_f256(const float* __restrict__ X) {
    int e = blockIdx.x;
    int k = threadIdx.x;
    int s = g_ei[e];
    int d = g_ei[EE + e];
    int r = g_et[e];
    atomicAdd(&g_B[((size_t)r * NN + d) * HH + k], X[(size_t)s * HH + k]);
}

__global__ void scatter_f11(const float* __restrict__ X) {
    int gid = blockIdx.x * blockDim.x + threadIdx.x;
    int e = gid >> 4;
    int k = gid & 15;
    if (e >= EE || k >= FIN) return;
    int s = g_ei[e];
    int d = g_ei[EE + e];
    int r = g_et[e];
    atomicAdd(&g_B[((size_t)r * NN + d) * FIN + k], X[(size_t)s * FIN + k]);
}

// ---------------- tf32 tensor-core GEMM: 128x128 CTA tile, 8 warps @ 32x64 ----------------
// C[row, bz*bsC + col] = sum_k A[bz][row,k] * W[bz][k,col] (+bias)(+Crd)(relu?)
#define TBM 128
#define TBN 128
#define TBK 32

__device__ __forceinline__ unsigned f2tf(float v) {
    unsigned r;
    asm("cvt.rna.tf32.f32 %0, %1;" : "=r"(r) : "f"(v));
    return r;
}

__device__ __forceinline__ void mma8(float* c, const unsigned* a, const unsigned* b) {
    asm volatile(
        "mma.sync.aligned.m16n8k8.row.col.f32.tf32.tf32.f32 "
        "{%0,%1,%2,%3}, {%4,%5,%6,%7}, {%8,%9}, {%0,%1,%2,%3};"
        : "+f"(c[0]), "+f"(c[1]), "+f"(c[2]), "+f"(c[3])
        : "r"(a[0]), "r"(a[1]), "r"(a[2]), "r"(a[3]), "r"(b[0]), "r"(b[1]));
}

__global__ void __launch_bounds__(256)
tgemm(const float* __restrict__ A, int M, int K, int lda, size_t bsA,
      const float* __restrict__ W, int ldw, size_t bsW,
      const float* __restrict__ Crd, float* __restrict__ Cwr,
      int ldc, int bsC,
      const float* __restrict__ bias, int relu)
{
    int bz = blockIdx.z;
    A += (size_t)bz * bsA;
    W += (size_t)bz * bsW;

    int rowBase = blockIdx.y * TBM;
    int colTile = blockIdx.x * TBN;   // local column within this batch's Hout

    // padded for conflict-free fragment loads (see strides: 36, 136)
    __shared__ unsigned As[TBM][36];   // As[m][k]
    __shared__ unsigned Bs[TBK][136];  // Bs[k][n]

    int tid = threadIdx.x;
    int lane = tid & 31;
    int warp = tid >> 5;
    int wr = (warp >> 1) * 32;   // warp row base within CTA tile
    int wc = (warp & 1) * 64;    // warp col base
    int gid = lane >> 2;         // 0..7
    int tq = lane & 3;           // 0..3

    float c[2][8][4];
#pragma unroll
    for (int i = 0; i < 2; i++)
#pragma unroll
        for (int j = 0; j < 8; j++)
#pragma unroll
            for (int q = 0; q < 4; q++) c[i][j][q] = 0.f;

    for (int k0 = 0; k0 < K; k0 += TBK) {
        // ---- load A tile 128x32 (row-major), convert to tf32 ----
        {
            int kq = (tid & 7) * 4;
            int rowq = tid >> 3;       // 0..31
#pragma unroll
            for (int p = 0; p < 4; p++) {
                int lr = rowq + p * 32;
                int row = rowBase + lr;
                const float* Ap = A + (size_t)row * lda + k0 + kq;
#pragma unroll
                for (int j = 0; j < 4; j++) {
                    float v = 0.f;
                    if (row < M && (k0 + kq + j) < K) v = Ap[j];
                    As[lr][kq + j] = f2tf(v);
                }
            }
        }
        // ---- load W tile 32x128, convert to tf32 ----
        {
            int nq = (tid & 31) * 4;
            int kk = tid >> 5;          // 0..7
#pragma unroll
            for (int p = 0; p < 4; p++) {
                int lk = kk + p * 8;
                const float* Wp = W + (size_t)(k0 + lk) * ldw + colTile + nq;
#pragma unroll
                for (int j = 0; j < 4; j++) {
                    float v = 0.f;
                    if ((k0 + lk) < K) v = Wp[j];
                    Bs[lk][nq + j] = f2tf(v);
                }
            }
        }
        __syncthreads();

#pragma unroll
        for (int ks = 0; ks < 4; ks++) {
            int kb = ks * 8;
            unsigned a[2][4], b[8][2];
#pragma unroll
            for (int rb = 0; rb < 2; rb++) {
                int r = wr + rb * 16 + gid;
                a[rb][0] = As[r][kb + tq];
                a[rb][1] = As[r + 8][kb + tq];
                a[rb][2] = As[r][kb + tq + 4];
                a[rb][3] = As[r + 8][kb + tq + 4];
            }
#pragma unroll
            for (int cb = 0; cb < 8; cb++) {
                int cn = wc + cb * 8 + gid;
                b[cb][0] = Bs[kb + tq][cn];
                b[cb][1] = Bs[kb + tq + 4][cn];
            }
#pragma unroll
            for (int rb = 0; rb < 2; rb++)
#pragma unroll
                for (int cb = 0; cb < 8; cb++)
                    mma8(c[rb][cb], a[rb], b[cb]);
        }
        __syncthreads();
    }

    // ---- epilogue ----
#pragma unroll
    for (int rb = 0; rb < 2; rb++) {
        int r0 = rowBase + wr + rb * 16 + gid;
        int r1 = r0 + 8;
#pragma unroll
        for (int cb = 0; cb < 8; cb++) {
            int lcol = colTile + wc + cb * 8 + tq * 2;
#pragma unroll
            for (int j = 0; j < 2; j++) {
                int col = lcol + j;
                float bsum = bias ? bias[col] : 0.f;
                if (r0 < M) {
                    size_t idx = (size_t)r0 * ldc + bz * bsC + col;
                    float v = c[rb][cb][j] + bsum;
                    if (Crd) v += Crd[idx];
                    if (relu) v = fmaxf(v, 0.f);
                    Cwr[idx] = v;
                }
                if (r1 < M) {
                    size_t idx = (size_t)r1 * ldc + bz * bsC + col;
                    float v = c[rb][cb][2 + j] + bsum;
                    if (Crd) v += Crd[idx];
                    if (relu) v = fmaxf(v, 0.f);
                    Cwr[idx] = v;
                }
            }
        }
    }
}

// ---------------- BatchNorm ----------------
__global__ void zero_stats() {
    int i = blockIdx.x * blockDim.x + threadIdx.x;
    if (i < 2 * RH) g_sums[i] = 0.f;
}

__global__ void bn_stats(const float* __restrict__ Hc) {
    int col = blockIdx.x * blockDim.x + threadIdx.x;  // gridDim.x*256 == RH
    float s = 0.f, q = 0.f;
    for (int row = blockIdx.y; row < NN; row += gridDim.y) {
        float v = Hc[(size_t)row * RH + col];
        s += v;
        q += v * v;
    }
    atomicAdd(&g_sums[col], s);
    atomicAdd(&g_sums[RH + col], q);
}

__global__ void bn_finalize(const float* __restrict__ g, const float* __restrict__ bt) {
    int c = blockIdx.x * blockDim.x + threadIdx.x;
    if (c < RH) {
        float mu  = g_sums[c] * (1.0f / NN);
        float var = g_sums[RH + c] * (1.0f / NN) - mu * mu;
        float sc  = g[c] * rsqrtf(var + BN_EPS);
        g_scale[c] = sc;
        g_shift[c] = bt[c] - mu * sc;
    }
}

__global__ void bn_apply() {
    size_t tot = (size_t)NN * RH / 4;
    float4* H4 = (float4*)g_Hcat;
    for (size_t i = (size_t)blockIdx.x * blockDim.x + threadIdx.x; i < tot;
         i += (size_t)gridDim.x * blockDim.x) {
        int c = ((int)(i & (RH / 4 - 1))) * 4;
        float4 v = H4[i];
        v.x = fmaxf(fmaf(v.x, g_scale[c + 0], g_shift[c + 0]), 0.f);
        v.y = fmaxf(fmaf(v.y, g_scale[c + 1], g_shift[c + 1]), 0.f);
        v.z = fmaxf(fmaf(v.z, g_scale[c + 2], g_shift[c + 2]), 0.f);
        v.w = fmaxf(fmaf(v.w, g_scale[c + 3], g_shift[c + 3]), 0.f);
        H4[i] = v;
    }
}

// bias0 = sb + sum_r b2_r   (b1 cancels inside BN, so it's dropped)
__global__ void bias0_kernel(const float* __restrict__ sb, const float* __restrict__ b2) {
    int c = threadIdx.x;
    g_bias0[c] = sb[c] + b2[c] + b2[HH + c] + b2[2 * HH + c] + b2[3 * HH + c];
}

// ---------------- pooling + final linear ----------------
__global__ void pool_zero() {
    int i = blockIdx.x * blockDim.x + threadIdx.x;
    if (i < GG * HH) g_pool[i] = 0.f;
    if (i < GG) g_cnt[i] = 0.f;
}

__global__ void pool_scatter(const float* __restrict__ X) {
    int n = blockIdx.x;
    int c = threadIdx.x;
    int b = g_batch[n];
    atomicAdd(&g_pool[b * HH + c], X[(size_t)n * HH + c]);
    if (c == 0) atomicAdd(&g_cnt[b], 1.f);
}

__global__ void final_linear(const float* __restrict__ lw, const float* __restrict__ lb,
                             float* __restrict__ out) {
    __shared__ float sh[HH];
    int g = blockIdx.x;
    float inv = 1.0f / fmaxf(g_cnt[g], 1.f);
    sh[threadIdx.x] = g_pool[g * HH + threadIdx.x] * inv;
    __syncthreads();
    if (threadIdx.x < TT) {
        int t = threadIdx.x;
        float acc = lb[t];
#pragma unroll 8
        for (int c = 0; c < HH; c++) acc += sh[c] * lw[c * TT + t];
        out[g * TT + t] = acc;
    }
}

// ---------------- orchestration ----------------
static void run_layer(const float* Xin, int fin,
                      const float* sw, const float* sb, const float* w1,
                      const float* gamma, const float* beta,
                      const float* w2, const float* b2,
                      float* pB, float* pHcat, float* pOUT, float* pBias0,
                      float* Xout)
{
    // 1. B[r] = X; B[r][dst] += X[src] over edges of type r
    copyB_kernel<<<4096, 256>>>(Xin, fin);
    if (fin == HH) {
        scatter_f256<<<EE, HH>>>(Xin);
    } else {
        scatter_f11<<<(EE * 16 + 255) / 256, 256>>>(Xin);
    }

    int mtiles = (NN + TBM - 1) / TBM;

    // 2. Hcat[:, r*H:(r+1)*H] = B[r] @ w1[r]    (b1 dropped: cancels in BN)
    tgemm<<<dim3(HH / TBN, mtiles, RR), 256>>>(
        pB, NN, fin, fin, (size_t)NN * fin,
        w1, HH, (size_t)fin * HH,
        nullptr, pHcat, RH, HH, nullptr, 0);

    // 3. BatchNorm (training stats) + ReLU, in place on Hcat
    zero_stats<<<2, 1024>>>();
    bn_stats<<<dim3(RH / 256, 128), 256>>>(pHcat);
    bn_finalize<<<4, 256>>>(gamma, beta);
    bn_apply<<<4096, 256>>>();

    // 4. bias0 = sb + sum_r b2_r
    bias0_kernel<<<1, 256>>>(sb, b2);

    // 5. OUT = Xin @ sw + bias0
    tgemm<<<dim3(HH / TBN, mtiles, 1), 256>>>(
        Xin, NN, fin, fin, 0,
        sw, HH, 0,
        nullptr, pOUT, HH, 0, pBias0, 0);

    // 6. Xout = relu(OUT + Hcat @ W2cat)   (W2 stacked [R*H, H] is contiguous)
    tgemm<<<dim3(HH / TBN, mtiles, 1), 256>>>(
        pHcat, NN, RH, RH, 0,
        w2, HH, 0,
        pOUT, Xout, HH, 0, nullptr, 1);
}

extern "C" void kernel_launch(void* const* d_in, const int* in_sizes, int n_in,
                              void* d_out, int out_size)
{
    const float* x     = (const float*)d_in[0];
    const int*   ei    = (const int*)d_in[1];   // int32 OR int64 raw words (sniffed)
    const int*   et    = (const int*)d_in[2];
    const int*   batch = (const int*)d_in[3];
    const float* lin_w = (const float*)d_in[28];
    const float* lin_b = (const float*)d_in[29];

    float *pB, *pHcat, *pX0, *pX1, *pOUT, *pBias0;
    cudaGetSymbolAddress((void**)&pB, g_B);
    cudaGetSymbolAddress((void**)&pHcat, g_Hcat);
    cudaGetSymbolAddress((void**)&pX0, g_X0);
    cudaGetSymbolAddress((void**)&pX1, g_X1);
    cudaGetSymbolAddress((void**)&pOUT, g_OUT);
    cudaGetSymbolAddress((void**)&pBias0, g_bias0);

    // normalize indices to int32 scratch (handles int32 or int64 inputs)
    convert_idx<<<1024, 256>>>(ei, et, batch);

    // layer params: base = 4 + 8*l : sw, sb, w1, b1(unused), g, bt, w2, b2
    const float* Xcur = x;
    float* outs[3] = {pX0, pX1, pX0};
    int fins[3] = {FIN, HH, HH};
    for (int l = 0; l < 3; l++) {
        int base = 4 + 8 * l;
        run_layer(Xcur, fins[l],
                  (const float*)d_in[base + 0], (const float*)d_in[base + 1],
                  (const float*)d_in[base + 2],
                  (const float*)d_in[base + 4], (const float*)d_in[base + 5],
                  (const float*)d_in[base + 6], (const float*)d_in[base + 7],
                  pB, pHcat, pOUT, pBias0, outs[l]);
        Xcur = outs[l];
    }

    // global mean pool + final linear
    pool_zero<<<(GG * HH + 255) / 256, 256>>>();
    pool_scatter<<<NN, HH>>>(Xcur);
    final_linear<<<GG, HH>>>(lin_w, lin_b, (float*)d_out);
}